// round 13
// baseline (speedup 1.0000x reference)
#include <cuda_runtime.h>
#include <math_constants.h>

// EvalEig: eigenvalues of 16 symmetric tridiagonal matrices (B=4, L=4, N=2000)
// SINGLE-SWEEP Sturm: 9 blocks/matrix x 128 threads (1 warp/SMSP). Each THREAD
// carries TWO independent packed f32x2 Sturm chains (4 probes) interleaved
// step-by-step, so the 4-cyc fma2 recurrence latency is hidden by the sibling
// chain -> issue-bound (~11 slots / dual-step for 4 probes). Each block covers
// 512 consecutive probes of a 4600-point split grid, then emits every
// eigenvalue bracketed by an adjacent probe pair at the bracket midpoint.
// Recurrence (scaled, offdiag=1): q_i = fma(sigma_i*(a_i-x), q_{i-1}, q_{i-2}),
// sigma=-1 odd i (sign subst q = eps*p, eps = +,-,-,+ period 4). Sign bits in
// two alternating masks (mA: odd/A steps, mB: even/B steps). Count per
// 32-step window (pairs ENDING at odd/A steps flip):
//   popc( (mA ^ mB)        & 0xFFFF) + popc(~(mB ^ (mA<<1)) & 0xFFFE)
// + (~(pB ^ (mA>>15)) & 1)

#define RN       2000
#define NMAT     16
#define NTHREADS 128
#define BLKS_PER_MAT 9
#define PROBE_STRIDE 511      // block j owns global probes [511j, 511j+511]
#define NGRID    4600         // last probe = 8*511+511 = 4599
#define NFINE    4000
#define FINE_W   4.85f
#define INV_B    0.0025f      // 1/400
#define BSCALE   400.0f

typedef unsigned long long u64;

__device__ __forceinline__ u64 pack2(float x, float y) {
    u64 r; asm("mov.b64 %0, {%1, %2};" : "=l"(r) : "f"(x), "f"(y)); return r;
}
__device__ __forceinline__ u64 add2(u64 a, u64 b) {
    u64 d; asm("add.rn.f32x2 %0, %1, %2;" : "=l"(d) : "l"(a), "l"(b)); return d;
}
__device__ __forceinline__ u64 fma2(u64 a, u64 b, u64 c) {
    u64 d; asm("fma.rn.f32x2 %0, %1, %2, %3;" : "=l"(d) : "l"(a), "l"(b), "l"(c)); return d;
}
__device__ __forceinline__ unsigned lo32(u64 x) { return (unsigned)x; }
__device__ __forceinline__ unsigned hi32(u64 x) { return (unsigned)(x >> 32); }

struct Tile { ulonglong2 v[8]; };   // 16 steps of {sa,sa}

__device__ __forceinline__ void load_tile(Tile& t, const ulonglong2* __restrict__ p) {
#pragma unroll
    for (int j = 0; j < 8; j++) t.v[j] = p[j];
}

// One packed Sturm chain (2 probes) with alternating sign masks.
struct Chain {
    u64 pxh, nxh;           // {+x1,+x2}, {-x1,-x2}
    u64 qc, qp;
    unsigned mAlo, mAhi, mBlo, mBhi;
    unsigned pBlo, pBhi;    // sign at last even step of previous window
    int clo, chi;

    __device__ __forceinline__ void init(float x1, float x2) {
        pxh = pack2(x1, x2); nxh = pack2(-x1, -x2);
        qp = 0; qc = pack2(1.0f, 1.0f);
        mAlo = mAhi = mBlo = mBhi = 0;
        pBlo = pBhi = 0; clo = chi = 0;
    }
    __device__ __forceinline__ void stepA(u64 v) {     // odd poly step
        u64 qn = fma2(add2(v, pxh), qc, qp);
        qp = qc; qc = qn;
        mAlo = __funnelshift_l(lo32(qc), mAlo, 1);
        mAhi = __funnelshift_l(hi32(qc), mAhi, 1);
    }
    __device__ __forceinline__ void stepB(u64 v) {     // even poly step
        u64 qn = fma2(add2(v, nxh), qc, qp);
        qp = qc; qc = qn;
        mBlo = __funnelshift_l(lo32(qc), mBlo, 1);
        mBhi = __funnelshift_l(hi32(qc), mBhi, 1);
    }
    __device__ __forceinline__ void rescale() {        // 2^(-ilogb(qc)), > 0
        unsigned eb0 = lo32(qc) & 0x7F800000u;
        unsigned eb1 = hi32(qc) & 0x7F800000u;
        float s0 = __uint_as_float(0x7F000000u - eb0);
        float s1 = __uint_as_float(0x7F000000u - eb1);
        qc = pack2(__uint_as_float(lo32(qc)) * s0, __uint_as_float(hi32(qc)) * s1);
        qp = pack2(__uint_as_float(lo32(qp)) * s0, __uint_as_float(hi32(qp)) * s1);
    }
    __device__ __forceinline__ void count32() {        // after 16 A + 16 B bits
        clo += __popc((mAlo ^ mBlo) & 0xFFFFu)                 // end-B: no flip
             + __popc((~(mBlo ^ (mAlo << 1))) & 0xFFFEu)       // end-A: flip
             + (int)((~(pBlo ^ (mAlo >> 15))) & 1u);           // boundary: flip
        chi += __popc((mAhi ^ mBhi) & 0xFFFFu)
             + __popc((~(mBhi ^ (mAhi << 1))) & 0xFFFEu)
             + (int)((~(pBhi ^ (mAhi >> 15))) & 1u);
        pBlo = mBlo & 1u; pBhi = mBhi & 1u;
    }
    __device__ __forceinline__ void count16() {        // tail: 8 A + 8 B bits
        clo += __popc((mAlo ^ mBlo) & 0xFFu)
             + __popc((~(mBlo ^ (mAlo << 1))) & 0xFEu)
             + (int)((~(pBlo ^ (mAlo >> 7))) & 1u);
        chi += __popc((mAhi ^ mBhi) & 0xFFu)
             + __popc((~(mBhi ^ (mAhi << 1))) & 0xFEu)
             + (int)((~(pBhi ^ (mAhi >> 7))) & 1u);
    }
};

// 16 steps of BOTH chains, interleaved (X then Y per A/B half-step), + rescale.
__device__ __forceinline__ void do16_dual(const Tile& t, Chain& X, Chain& Y) {
#pragma unroll
    for (int j = 0; j < 8; j++) {
        X.stepA(t.v[j].x);
        Y.stepA(t.v[j].x);
        X.stepB(t.v[j].y);
        Y.stepB(t.v[j].y);
    }
    X.rescale();
    Y.rescale();
}

// Four packed Sturm counts at x[0..3] -> c[0..3]; ping-pong prefetched tiles.
__device__ __forceinline__ void sturm4(const u64* __restrict__ sdp,
                                       float x0, float x1, float x2, float x3,
                                       int* c) {
    const ulonglong2* __restrict__ p = reinterpret_cast<const ulonglong2*>(sdp);
    Chain X, Y;
    X.init(x0, x1);
    Y.init(x2, x3);

    Tile A, B;
    load_tile(A, p);
#pragma unroll 1
    for (int w = 0; w < 62; w++) {        // 32-step window; preload next tiles
        load_tile(B, p + (2 * w + 1) * 8);
        do16_dual(A, X, Y);
        load_tile(A, p + (2 * w + 2) * 8);
        do16_dual(B, X, Y);
        X.count32();
        Y.count32();
    }
    do16_dual(A, X, Y);                   // 16-step tail (steps 1985..2000)
    X.count16();
    Y.count16();
    c[0] = X.clo; c[1] = X.chi; c[2] = Y.clo; c[3] = Y.chi;
}

__global__ __launch_bounds__(NTHREADS, 1)
void eval_eig_kernel(const float* __restrict__ ptl, float* __restrict__ out) {
    __shared__ __align__(16) u64 sdp[RN];      // {sigma_i*a_i, same} packed
    __shared__ int   sc[4 * NTHREADS];         // counts at this block's probes
    __shared__ float wmin[NTHREADS / 32], wmax[NTHREADS / 32];
    __shared__ float bounds[2];

    const int mat = blockIdx.y;                // 0..15 -> (b, l)
    const int b   = mat >> 2;
    const int l   = mat & 3;
    const float ll1 = (float)(l * (l + 1));
    const int t   = threadIdx.x;

    // Scaled, signed, duplicated diagonal; Gershgorin min/max of a.
    // Bitwise-identical across the matrix's 9 blocks (boundary determinism).
    const float step = 99.95f / 1999.0f;       // jnp.linspace(0.05, 100, 2000)
    float lmin = CUDART_INF_F, lmax = -CUDART_INF_F;
    for (int i = t; i < RN; i += NTHREADS) {
        float r  = 0.05f + step * (float)i;
        float a  = (800.0f + ptl[b * RN + i] + ll1 / (r * r)) * INV_B;
        float sa = (i & 1) ? a : -a;
        sdp[i] = pack2(sa, sa);
        lmin = fminf(lmin, a);
        lmax = fmaxf(lmax, a);
    }
#pragma unroll
    for (int off = 16; off; off >>= 1) {
        lmin = fminf(lmin, __shfl_xor_sync(0xffffffffu, lmin, off));
        lmax = fmaxf(lmax, __shfl_xor_sync(0xffffffffu, lmax, off));
    }
    const int wid = t >> 5;
    if ((t & 31) == 0) { wmin[wid] = lmin; wmax[wid] = lmax; }
    __syncthreads();
    if (t == 0) {
        float a = wmin[0], c = wmax[0];
#pragma unroll
        for (int w = 1; w < NTHREADS / 32; w++) {
            a = fminf(a, wmin[w]);
            c = fmaxf(c, wmax[w]);
        }
        bounds[0] = a - 2.001f;    // count(b0)=0
        bounds[1] = c + 2.001f;    // count(b1)=RN
    }
    __syncthreads();

    const float b0 = bounds[0];
    const float b1 = bounds[1];
    const float cs = fminf(b0 + FINE_W, b1);
    const float gwf = (cs - b0) * (1.0f / (float)NFINE);
    const float gwc = (b1 - cs) * (1.0f / (float)(NGRID - 1 - NFINE));

    auto gridx = [&](int g) -> float {
        return (g <= NFINE) ? b0 + gwf * (float)g
                            : cs + gwc * (float)(g - NFINE);
    };

    // ---- The ONE sweep: this block's 512 probes (4 per thread, dual packed) ----
    const int g0 = blockIdx.x * PROBE_STRIDE;
    {
        int c4[4];
        sturm4(sdp, gridx(g0 + 4 * t),     gridx(g0 + 4 * t + 1),
                    gridx(g0 + 4 * t + 2), gridx(g0 + 4 * t + 3), c4);
        sc[4 * t]     = c4[0];
        sc[4 * t + 1] = c4[1];
        sc[4 * t + 2] = c4[2];
        sc[4 * t + 3] = c4[3];
    }
    __syncthreads();

    // ---- Emit: pair (u, u+1), u = 0..510, brackets eigenvalues
    // [sc[u], sc[u+1]) at midpoint. Integer-walk telescoping + duplicated
    // boundary probes (bitwise-identical across blocks) cover all k in [0,RN).
#pragma unroll
    for (int h = 0; h < 4; h++) {
        int u = 4 * t + h;
        if (u < 4 * NTHREADS - 1) {
            int cL = sc[u], cR = sc[u + 1];
            if (cR > cL) {
                float xm = 0.5f * (gridx(g0 + u) + gridx(g0 + u + 1)) * BSCALE;
                for (int k = cL; k < cR; k++) out[mat * RN + k] = xm;
            }
        }
    }
}

extern "C" void kernel_launch(void* const* d_in, const int* in_sizes, int n_in,
                              void* d_out, int out_size) {
    (void)in_sizes; (void)n_in; (void)out_size;
    const float* ptl = (const float*)d_in[0];
    float* out = (float*)d_out;
    dim3 grid(BLKS_PER_MAT, NMAT);   // (9, 16) = 144 blocks, 128 threads
    eval_eig_kernel<<<grid, NTHREADS>>>(ptl, out);
}

// round 14
// speedup vs baseline: 1.5225x; 1.5225x over previous
#include <cuda_runtime.h>
#include <math_constants.h>

// EvalEig: eigenvalues of 16 symmetric tridiagonal matrices (B=4, L=4, N=2000)
// SEGMENTED single-sweep Sturm. 9 blocks/matrix x 256 threads. The 2000-step
// recurrence is split across two warp groups working on the SAME probes:
//   threads [0,128):   segment A = Sturm pairs 1..1056 (exact, fresh start)
//   threads [128,256): segment B = pairs 1057..2000, computed from a fresh
//     start at step 961 with 96 WARM-UP steps (counts discarded). By the
//     rank-1 boundary inertia bound the summed count cA+cB differs from the
//     true count by at most +-1, and only rarely (warm-up re-locks the
//     recurrence); the emit's coverage rule (last u with c[u]<=k) tolerates
//     non-monotone blips without gaps.
// Each thread evaluates 2 packed probes; block covers 256 probes of a
// 2296-point split grid (4.85-wide fine band, R11 geometry). Emit: every
// adjacent probe pair writes its bracketed eigenvalues at the midpoint.
// Recurrence (scaled, offdiag=1): q_i = fma(sigma_i*(a_i-x), q_{i-1}, q_{i-2}),
// sigma=-1 odd i; fresh start at 961 (= 1 mod 4) preserves sign parity.

#define RN       2000
#define NMAT     16
#define NTHREADS 256
#define HALF_T   128
#define BLKS_PER_MAT 9
#define PROBE_STRIDE 255      // block j owns global probes [255j, 255j+255]
#define NGRID    2296
#define NFINE    2000
#define FINE_W   4.85f
#define INV_B    0.0025f      // 1/400
#define BSCALE   400.0f
// Segment A: 33 windows (steps 1..1056). Segment B: tiles from row 960,
// 32 windows + 16-tail (steps 961..2000); first 3 windows (96 steps) warm-up.
#define SEGA_WIN 33
#define SEGB_TILE0 60         // row 960 -> 16-step tile index 60
#define SEGB_WIN 32
#define SEGB_WARM 3

typedef unsigned long long u64;

__device__ __forceinline__ u64 pack2(float x, float y) {
    u64 r; asm("mov.b64 %0, {%1, %2};" : "=l"(r) : "f"(x), "f"(y)); return r;
}
__device__ __forceinline__ u64 add2(u64 a, u64 b) {
    u64 d; asm("add.rn.f32x2 %0, %1, %2;" : "=l"(d) : "l"(a), "l"(b)); return d;
}
__device__ __forceinline__ u64 fma2(u64 a, u64 b, u64 c) {
    u64 d; asm("fma.rn.f32x2 %0, %1, %2, %3;" : "=l"(d) : "l"(a), "l"(b), "l"(c)); return d;
}
__device__ __forceinline__ unsigned lo32(u64 x) { return (unsigned)x; }
__device__ __forceinline__ unsigned hi32(u64 x) { return (unsigned)(x >> 32); }

struct Tile { ulonglong2 v[8]; };   // 16 steps of {sa,sa}

__device__ __forceinline__ void load_tile(Tile& t, const ulonglong2* __restrict__ p) {
#pragma unroll
    for (int j = 0; j < 8; j++) t.v[j] = p[j];
}

// 16 recurrence steps (8 A/B double-steps) + exponent-hack rescale.
__device__ __forceinline__ void do16(const Tile& t, u64 pxh, u64 nxh,
                                     u64& qc, u64& qp,
                                     unsigned& mAlo, unsigned& mAhi,
                                     unsigned& mBlo, unsigned& mBhi) {
#pragma unroll
    for (int j = 0; j < 8; j++) {
        u64 qn = fma2(add2(t.v[j].x, pxh), qc, qp);   // odd poly step
        qp = qc; qc = qn;
        mAlo = __funnelshift_l(lo32(qc), mAlo, 1);
        mAhi = __funnelshift_l(hi32(qc), mAhi, 1);
        qn = fma2(add2(t.v[j].y, nxh), qc, qp);       // even poly step
        qp = qc; qc = qn;
        mBlo = __funnelshift_l(lo32(qc), mBlo, 1);
        mBhi = __funnelshift_l(hi32(qc), mBhi, 1);
    }
    unsigned eb0 = lo32(qc) & 0x7F800000u;
    unsigned eb1 = hi32(qc) & 0x7F800000u;
    float s0 = __uint_as_float(0x7F000000u - eb0);    // 2^(-ilogb), > 0
    float s1 = __uint_as_float(0x7F000000u - eb1);
    qc = pack2(__uint_as_float(lo32(qc)) * s0, __uint_as_float(hi32(qc)) * s1);
    qp = pack2(__uint_as_float(lo32(qp)) * s0, __uint_as_float(hi32(qp)) * s1);
}

#define COUNT32()                                                            \
    do {                                                                     \
        clo += __popc((mAlo ^ mBlo) & 0xFFFFu)                               \
             + __popc((~(mBlo ^ (mAlo << 1))) & 0xFFFEu)                     \
             + (int)((~(pBlo ^ (mAlo >> 15))) & 1u);                         \
        chi += __popc((mAhi ^ mBhi) & 0xFFFFu)                               \
             + __popc((~(mBhi ^ (mAhi << 1))) & 0xFFFEu)                     \
             + (int)((~(pBhi ^ (mAhi >> 15))) & 1u);                         \
        pBlo = mBlo & 1u; pBhi = mBhi & 1u;                                  \
    } while (0)

// Segment A: windows 0..SEGA_WIN-1 (steps 1..1056), all counted.
__device__ __forceinline__ void sturm2_segA(const u64* __restrict__ sdp,
                                            float x1, float x2, int& c1, int& c2) {
    const u64 pxh = pack2( x1,  x2);
    const u64 nxh = pack2(-x1, -x2);
    const ulonglong2* __restrict__ p = reinterpret_cast<const ulonglong2*>(sdp);
    u64 qp = 0, qc = pack2(1.0f, 1.0f);
    unsigned mAlo = 0, mAhi = 0, mBlo = 0, mBhi = 0, pBlo = 0, pBhi = 0;
    int clo = 0, chi = 0;

    Tile A, B;
    load_tile(A, p);
#pragma unroll 1
    for (int w = 0; w < SEGA_WIN; w++) {
        load_tile(B, p + (2 * w + 1) * 8);
        do16(A, pxh, nxh, qc, qp, mAlo, mAhi, mBlo, mBhi);
        load_tile(A, p + (2 * w + 2) * 8);    // max half 66 < 125: in bounds
        do16(B, pxh, nxh, qc, qp, mAlo, mAhi, mBlo, mBhi);
        COUNT32();
    }
    c1 = clo; c2 = chi;
}

// Segment B: fresh start at step 961 (tile 60); 3 warm-up windows (counts
// reset after window 2), 29 counted windows, then 16-step tail.
__device__ __forceinline__ void sturm2_segB(const u64* __restrict__ sdp,
                                            float x1, float x2, int& c1, int& c2) {
    const u64 pxh = pack2( x1,  x2);
    const u64 nxh = pack2(-x1, -x2);
    const ulonglong2* __restrict__ p =
        reinterpret_cast<const ulonglong2*>(sdp) + SEGB_TILE0 * 8;
    u64 qp = 0, qc = pack2(1.0f, 1.0f);
    unsigned mAlo = 0, mAhi = 0, mBlo = 0, mBhi = 0, pBlo = 0, pBhi = 0;
    int clo = 0, chi = 0;

    Tile A, B;
    load_tile(A, p);
#pragma unroll 1
    for (int w = 0; w < SEGB_WIN; w++) {
        load_tile(B, p + (2 * w + 1) * 8);
        do16(A, pxh, nxh, qc, qp, mAlo, mAhi, mBlo, mBhi);
        load_tile(A, p + (2 * w + 2) * 8);    // max rel half 64 = abs 124 ✓
        do16(B, pxh, nxh, qc, qp, mAlo, mAhi, mBlo, mBhi);
        COUNT32();
        if (w == SEGB_WARM - 1) { clo = 0; chi = 0; }   // discard warm-up
    }
    // 16-step tail (steps 1985..2000), rel half 64 already in A.
    do16(A, pxh, nxh, qc, qp, mAlo, mAhi, mBlo, mBhi);
    clo += __popc((mAlo ^ mBlo) & 0xFFu)
         + __popc((~(mBlo ^ (mAlo << 1))) & 0xFEu)
         + (int)((~(pBlo ^ (mAlo >> 7))) & 1u);
    chi += __popc((mAhi ^ mBhi) & 0xFFu)
         + __popc((~(mBhi ^ (mAhi << 1))) & 0xFEu)
         + (int)((~(pBhi ^ (mAhi >> 7))) & 1u);
    c1 = clo; c2 = chi;
}

__global__ __launch_bounds__(NTHREADS, 1)
void eval_eig_kernel(const float* __restrict__ ptl, float* __restrict__ out) {
    __shared__ __align__(16) u64 sdp[RN];      // {sigma_i*a_i, same} packed
    __shared__ int   scA[2 * HALF_T];          // segment-A counts per probe
    __shared__ int   scB[2 * HALF_T];          // segment-B counts per probe
    __shared__ float wmin[NTHREADS / 32], wmax[NTHREADS / 32];
    __shared__ float bounds[2];

    const int mat = blockIdx.y;                // 0..15 -> (b, l)
    const int b   = mat >> 2;
    const int l   = mat & 3;
    const float ll1 = (float)(l * (l + 1));
    const int t   = threadIdx.x;

    // Scaled, signed, duplicated diagonal; Gershgorin min/max of a.
    // Bitwise-identical across the matrix's 9 blocks (boundary determinism).
    const float step = 99.95f / 1999.0f;       // jnp.linspace(0.05, 100, 2000)
    float lmin = CUDART_INF_F, lmax = -CUDART_INF_F;
    for (int i = t; i < RN; i += NTHREADS) {
        float r  = 0.05f + step * (float)i;
        float a  = (800.0f + ptl[b * RN + i] + ll1 / (r * r)) * INV_B;
        float sa = (i & 1) ? a : -a;
        sdp[i] = pack2(sa, sa);
        lmin = fminf(lmin, a);
        lmax = fmaxf(lmax, a);
    }
#pragma unroll
    for (int off = 16; off; off >>= 1) {
        lmin = fminf(lmin, __shfl_xor_sync(0xffffffffu, lmin, off));
        lmax = fmaxf(lmax, __shfl_xor_sync(0xffffffffu, lmax, off));
    }
    const int wid = t >> 5;
    if ((t & 31) == 0) { wmin[wid] = lmin; wmax[wid] = lmax; }
    __syncthreads();
    if (t == 0) {
        float a = wmin[0], c = wmax[0];
#pragma unroll
        for (int w = 1; w < NTHREADS / 32; w++) {
            a = fminf(a, wmin[w]);
            c = fmaxf(c, wmax[w]);
        }
        bounds[0] = a - 2.001f;    // count(b0)=0
        bounds[1] = c + 2.001f;    // count(b1)=RN
    }
    __syncthreads();

    const float b0 = bounds[0];
    const float b1 = bounds[1];
    const float cs = fminf(b0 + FINE_W, b1);
    const float gwf = (cs - b0) * (1.0f / (float)NFINE);
    const float gwc = (b1 - cs) * (1.0f / (float)(NGRID - 1 - NFINE));

    auto gridx = [&](int g) -> float {
        return (g <= NFINE) ? b0 + gwf * (float)g
                            : cs + gwc * (float)(g - NFINE);
    };

    // ---- The segmented sweep: 256 probes/block, 2 per thread, 2 segments ----
    const int g0  = blockIdx.x * PROBE_STRIDE;
    const int pid = t & (HALF_T - 1);
    {
        float x1 = gridx(g0 + 2 * pid);
        float x2 = gridx(g0 + 2 * pid + 1);
        int c1, c2;
        if (t < HALF_T) {
            sturm2_segA(sdp, x1, x2, c1, c2);
            scA[2 * pid] = c1; scA[2 * pid + 1] = c2;
        } else {
            sturm2_segB(sdp, x1, x2, c1, c2);
            scB[2 * pid] = c1; scB[2 * pid + 1] = c2;
        }
    }
    __syncthreads();

    // ---- Emit (lower half threads): pair (u, u+1) writes eigenvalues
    // [c[u], c[u+1]) at the bracket midpoint. Coverage: for any k, the last u
    // with c[u] <= k has c[u+1] > k, so k is always written (c[0]=0 at the
    // global left edge, c[last]=RN at the right; boundary probes duplicated
    // bitwise across blocks).
    if (t < HALF_T) {
#pragma unroll
        for (int h = 0; h < 2; h++) {
            int u = 2 * pid + h;
            if (u < 2 * HALF_T - 1) {
                int cL = scA[u] + scB[u];
                int cR = scA[u + 1] + scB[u + 1];
                if (cR > cL) {
                    float xm = 0.5f * (gridx(g0 + u) + gridx(g0 + u + 1)) * BSCALE;
                    cL = max(cL, 0); cR = min(cR, RN);
                    for (int k = cL; k < cR; k++) out[mat * RN + k] = xm;
                }
            }
        }
    }
}

extern "C" void kernel_launch(void* const* d_in, const int* in_sizes, int n_in,
                              void* d_out, int out_size) {
    (void)in_sizes; (void)n_in; (void)out_size;
    const float* ptl = (const float*)d_in[0];
    float* out = (float*)d_out;
    dim3 grid(BLKS_PER_MAT, NMAT);   // (9, 16) = 144 blocks, 256 threads
    eval_eig_kernel<<<grid, NTHREADS>>>(ptl, out);
}

// round 15
// speedup vs baseline: 1.5431x; 1.0135x over previous
#include <cuda_runtime.h>
#include <math_constants.h>

// EvalEig: eigenvalues of 16 symmetric tridiagonal matrices (B=4, L=4, N=2000)
// 3-SEGMENT single-sweep Sturm. 9 blocks/matrix x 384 threads; the 2000-step
// recurrence is split across three warp groups on the SAME probes:
//   group 0: pairs    1.. 672  (exact fresh start)            672 steps
//   group 1: pairs  673..1344  (fresh start @577, 96 warm-up) 768 steps
//   group 2: pairs 1345..2000  (fresh start @1249, 96 warm-up)752 steps
// Warm-up counts discarded; each interior boundary contributes at most a +-1
// count blip (interlacing), which the emit coverage rule tolerates.
// Each thread: 2 packed probes; block covers 256 probes of a 2296-point
// split grid. Emit: adjacent probe pairs write bracketed eigenvalues at the
// bracket midpoint. Recurrence (scaled, offdiag=1):
//   q_i = fma(sigma_i*(a_i - x), q_{i-1}, q_{i-2}), sigma=-1 odd i.
// Fresh starts at even 16-step tiles keep step == 1 mod 4 (sign parity ok).

#define RN       2000
#define NMAT     16
#define NTHREADS 384
#define GRP_T    128
#define BLKS_PER_MAT 9
#define PROBE_STRIDE 255      // block j owns global probes [255j, 255j+255]
#define NGRID    2296
#define NFINE    2000
#define FINE_W   4.85f
#define INV_B    0.0025f      // 1/400
#define BSCALE   400.0f

typedef unsigned long long u64;

__device__ __forceinline__ u64 pack2(float x, float y) {
    u64 r; asm("mov.b64 %0, {%1, %2};" : "=l"(r) : "f"(x), "f"(y)); return r;
}
__device__ __forceinline__ u64 add2(u64 a, u64 b) {
    u64 d; asm("add.rn.f32x2 %0, %1, %2;" : "=l"(d) : "l"(a), "l"(b)); return d;
}
__device__ __forceinline__ u64 fma2(u64 a, u64 b, u64 c) {
    u64 d; asm("fma.rn.f32x2 %0, %1, %2, %3;" : "=l"(d) : "l"(a), "l"(b), "l"(c)); return d;
}
__device__ __forceinline__ unsigned lo32(u64 x) { return (unsigned)x; }
__device__ __forceinline__ unsigned hi32(u64 x) { return (unsigned)(x >> 32); }

struct Tile { ulonglong2 v[8]; };   // 16 steps of {sa,sa}

__device__ __forceinline__ void load_tile(Tile& t, const ulonglong2* __restrict__ p) {
#pragma unroll
    for (int j = 0; j < 8; j++) t.v[j] = p[j];
}

// 16 recurrence steps (8 A/B double-steps) + exponent-hack rescale.
__device__ __forceinline__ void do16(const Tile& t, u64 pxh, u64 nxh,
                                     u64& qc, u64& qp,
                                     unsigned& mAlo, unsigned& mAhi,
                                     unsigned& mBlo, unsigned& mBhi) {
#pragma unroll
    for (int j = 0; j < 8; j++) {
        u64 qn = fma2(add2(t.v[j].x, pxh), qc, qp);   // odd poly step
        qp = qc; qc = qn;
        mAlo = __funnelshift_l(lo32(qc), mAlo, 1);
        mAhi = __funnelshift_l(hi32(qc), mAhi, 1);
        qn = fma2(add2(t.v[j].y, nxh), qc, qp);       // even poly step
        qp = qc; qc = qn;
        mBlo = __funnelshift_l(lo32(qc), mBlo, 1);
        mBhi = __funnelshift_l(hi32(qc), mBhi, 1);
    }
    unsigned eb0 = lo32(qc) & 0x7F800000u;
    unsigned eb1 = hi32(qc) & 0x7F800000u;
    float s0 = __uint_as_float(0x7F000000u - eb0);    // 2^(-ilogb), > 0
    float s1 = __uint_as_float(0x7F000000u - eb1);
    qc = pack2(__uint_as_float(lo32(qc)) * s0, __uint_as_float(hi32(qc)) * s1);
    qp = pack2(__uint_as_float(lo32(qp)) * s0, __uint_as_float(hi32(qp)) * s1);
}

// Generic segment: nwin 32-step windows starting at 16-step tile tile0 (must
// be even), first warm windows discarded, optional 16-step tail.
__device__ __forceinline__ void sturm2_seg(const u64* __restrict__ sdp,
                                           float x1, float x2,
                                           int tile0, int nwin, int warm, bool tail,
                                           int& c1, int& c2) {
    const u64 pxh = pack2( x1,  x2);
    const u64 nxh = pack2(-x1, -x2);
    const ulonglong2* __restrict__ p =
        reinterpret_cast<const ulonglong2*>(sdp) + tile0 * 8;
    u64 qp = 0, qc = pack2(1.0f, 1.0f);
    unsigned mAlo = 0, mAhi = 0, mBlo = 0, mBhi = 0, pBlo = 0, pBhi = 0;
    int clo = 0, chi = 0;

    Tile A, B;
    load_tile(A, p);
#pragma unroll 1
    for (int w = 0; w < nwin; w++) {
        load_tile(B, p + (2 * w + 1) * 8);
        do16(A, pxh, nxh, qc, qp, mAlo, mAhi, mBlo, mBhi);
        load_tile(A, p + (2 * w + 2) * 8);     // stays within sdp (see callers)
        do16(B, pxh, nxh, qc, qp, mAlo, mAhi, mBlo, mBhi);
        clo += __popc((mAlo ^ mBlo) & 0xFFFFu)
             + __popc((~(mBlo ^ (mAlo << 1))) & 0xFFFEu)
             + (int)((~(pBlo ^ (mAlo >> 15))) & 1u);
        chi += __popc((mAhi ^ mBhi) & 0xFFFFu)
             + __popc((~(mBhi ^ (mAhi << 1))) & 0xFFFEu)
             + (int)((~(pBhi ^ (mAhi >> 15))) & 1u);
        pBlo = mBlo & 1u; pBhi = mBhi & 1u;
        if (w == warm - 1) { clo = 0; chi = 0; }   // discard warm-up
    }
    if (tail) {   // 16 more steps (8 A-bits, 8 B-bits)
        do16(A, pxh, nxh, qc, qp, mAlo, mAhi, mBlo, mBhi);
        clo += __popc((mAlo ^ mBlo) & 0xFFu)
             + __popc((~(mBlo ^ (mAlo << 1))) & 0xFEu)
             + (int)((~(pBlo ^ (mAlo >> 7))) & 1u);
        chi += __popc((mAhi ^ mBhi) & 0xFFu)
             + __popc((~(mBhi ^ (mAhi << 1))) & 0xFEu)
             + (int)((~(pBhi ^ (mAhi >> 7))) & 1u);
    }
    c1 = clo; c2 = chi;
}

__global__ __launch_bounds__(NTHREADS, 1)
void eval_eig_kernel(const float* __restrict__ ptl, float* __restrict__ out) {
    __shared__ __align__(16) u64 sdp[RN];      // {sigma_i*a_i, same} packed
    __shared__ int   sc[3][2 * GRP_T];         // per-segment counts per probe
    __shared__ float wmin[NTHREADS / 32], wmax[NTHREADS / 32];
    __shared__ float bounds[2];

    const int mat = blockIdx.y;                // 0..15 -> (b, l)
    const int b   = mat >> 2;
    const int l   = mat & 3;
    const float ll1 = (float)(l * (l + 1));
    const int t   = threadIdx.x;

    // Scaled, signed, duplicated diagonal; Gershgorin min/max of a.
    // Bitwise-identical across the matrix's 9 blocks (boundary determinism).
    const float step = 99.95f / 1999.0f;       // jnp.linspace(0.05, 100, 2000)
    float lmin = CUDART_INF_F, lmax = -CUDART_INF_F;
    for (int i = t; i < RN; i += NTHREADS) {
        float r  = 0.05f + step * (float)i;
        float a  = (800.0f + ptl[b * RN + i] + ll1 / (r * r)) * INV_B;
        float sa = (i & 1) ? a : -a;
        sdp[i] = pack2(sa, sa);
        lmin = fminf(lmin, a);
        lmax = fmaxf(lmax, a);
    }
#pragma unroll
    for (int off = 16; off; off >>= 1) {
        lmin = fminf(lmin, __shfl_xor_sync(0xffffffffu, lmin, off));
        lmax = fmaxf(lmax, __shfl_xor_sync(0xffffffffu, lmax, off));
    }
    const int wid = t >> 5;
    if ((t & 31) == 0) { wmin[wid] = lmin; wmax[wid] = lmax; }
    __syncthreads();
    if (t == 0) {
        float a = wmin[0], c = wmax[0];
#pragma unroll
        for (int w = 1; w < NTHREADS / 32; w++) {
            a = fminf(a, wmin[w]);
            c = fmaxf(c, wmax[w]);
        }
        bounds[0] = a - 2.001f;    // count(b0)=0
        bounds[1] = c + 2.001f;    // count(b1)=RN
    }
    __syncthreads();

    const float b0 = bounds[0];
    const float b1 = bounds[1];
    const float cs = fminf(b0 + FINE_W, b1);
    const float gwf = (cs - b0) * (1.0f / (float)NFINE);
    const float gwc = (b1 - cs) * (1.0f / (float)(NGRID - 1 - NFINE));

    auto gridx = [&](int g) -> float {
        return (g <= NFINE) ? b0 + gwf * (float)g
                            : cs + gwc * (float)(g - NFINE);
    };

    // ---- Segmented sweep: 256 probes/block, 2/thread, 3 segments ----
    // Seg 0: tiles  0..41,  21 windows, warm 0, no tail  (steps    1.. 672)
    // Seg 1: tiles 36..83,  24 windows, warm 3, no tail  (steps  577..1344,
    //                                                     counted 673..1344)
    // Seg 2: tiles 78..124, 23 windows, warm 3, +tail    (steps 1249..2000,
    //                                                     counted 1345..2000)
    const int g0  = blockIdx.x * PROBE_STRIDE;
    const int grp = t / GRP_T;                 // 0,1,2
    const int pid = t % GRP_T;
    {
        float x1 = gridx(g0 + 2 * pid);
        float x2 = gridx(g0 + 2 * pid + 1);
        int c1, c2;
        if (grp == 0)      sturm2_seg(sdp, x1, x2,  0, 21, 0, false, c1, c2);
        else if (grp == 1) sturm2_seg(sdp, x1, x2, 36, 24, 3, false, c1, c2);
        else               sturm2_seg(sdp, x1, x2, 78, 23, 3, true,  c1, c2);
        sc[grp][2 * pid]     = c1;
        sc[grp][2 * pid + 1] = c2;
    }
    __syncthreads();

    // ---- Emit (group 0): pair (u, u+1) writes eigenvalues [c[u], c[u+1])
    // at the bracket midpoint. Coverage: the last u with c[u] <= k has
    // c[u+1] > k (c sums to 0 at global left edge, RN at right; boundary
    // probes bitwise-duplicated across blocks), so every k is written even
    // with +-1 boundary blips.
    if (grp == 0) {
#pragma unroll
        for (int h = 0; h < 2; h++) {
            int u = 2 * pid + h;
            if (u < 2 * GRP_T - 1) {
                int cL = sc[0][u] + sc[1][u] + sc[2][u];
                int cR = sc[0][u + 1] + sc[1][u + 1] + sc[2][u + 1];
                if (cR > cL) {
                    float xm = 0.5f * (gridx(g0 + u) + gridx(g0 + u + 1)) * BSCALE;
                    cL = max(cL, 0); cR = min(cR, RN);
                    for (int k = cL; k < cR; k++) out[mat * RN + k] = xm;
                }
            }
        }
    }
}

extern "C" void kernel_launch(void* const* d_in, const int* in_sizes, int n_in,
                              void* d_out, int out_size) {
    (void)in_sizes; (void)n_in; (void)out_size;
    const float* ptl = (const float*)d_in[0];
    float* out = (float*)d_out;
    dim3 grid(BLKS_PER_MAT, NMAT);   // (9, 16) = 144 blocks, 384 threads
    eval_eig_kernel<<<grid, NTHREADS>>>(ptl, out);
}